// round 5
// baseline (speedup 1.0000x reference)
#include <cuda_runtime.h>
#include <cuda_fp16.h>
#include <cstdint>

#define HID 1024
#define VOC 32000
#define NL  3
#define NB  64
#define NT  32
#define K3H (3*HID)

// ---------------- device scratch (static, allocation-free) ----------------
__device__ __align__(16) __half g_Wih16[NL * K3H * HID];
__device__ __align__(16) __half g_Whh16[NL * K3H * HID];
__device__ __align__(16) __half g_Wout16[VOC * HID];
__device__ __align__(16) __half g_x16a[NB * NT * HID];
__device__ __align__(16) __half g_x16b[NB * NT * HID];
__device__ __align__(16) float  g_xp[NB * NT * K3H];
__device__ __align__(16) __half g_h16a[NB * HID];
__device__ __align__(16) __half g_h16b[NB * HID];

// grid barrier state (generation-based; never needs host reset)
__device__ unsigned g_bar_cnt = 0;
__device__ unsigned g_bar_gen = 0;

// ---------------- helpers ----------------
__device__ __forceinline__ uint32_t smem_u32(const void* p) {
    return (uint32_t)__cvta_generic_to_shared(p);
}
__device__ __forceinline__ void cp16(uint32_t d, const void* s) {
    asm volatile("cp.async.cg.shared.global [%0], [%1], 16;\n" :: "r"(d), "l"(s));
}
__device__ __forceinline__ void cp_commit() {
    asm volatile("cp.async.commit_group;\n" ::: "memory");
}
__device__ __forceinline__ void mma16816(float* c, const uint32_t* a, const uint32_t* b) {
    asm volatile(
        "mma.sync.aligned.m16n8k16.row.col.f32.f16.f16.f32 "
        "{%0,%1,%2,%3},{%4,%5,%6,%7},{%8,%9},{%0,%1,%2,%3};\n"
        : "+f"(c[0]), "+f"(c[1]), "+f"(c[2]), "+f"(c[3])
        : "r"(a[0]), "r"(a[1]), "r"(a[2]), "r"(a[3]), "r"(b[0]), "r"(b[1]));
}

// ---------------- f32 -> f16 weight convert ----------------
__global__ void k_cvt(const float* __restrict__ src, int dstSel, int n) {
    int i = (blockIdx.x * 256 + threadIdx.x) * 4;
    if (i >= n) return;
    __half* dst = (dstSel == 0) ? g_Wih16 : (dstSel == 1) ? g_Whh16 : g_Wout16;
    float4 v = *(const float4*)(src + i);
    *(__half2*)(dst + i)     = __floats2half2_rn(v.x, v.y);
    *(__half2*)(dst + i + 2) = __floats2half2_rn(v.z, v.w);
}

// ---------------- embedding + relu -> x16a ----------------
__global__ void k_embed(const float* __restrict__ emb, const int* __restrict__ target) {
    int row = blockIdx.x;           // 0..NB*NT-1
    int b = row >> 5, t = row & 31; // NT = 32
    int id = (t == 0) ? 0 : target[b * NT + t - 1];
    const float* src = emb + (size_t)id * HID;
    __half* dst = g_x16a + (size_t)row * HID;
    int i = threadIdx.x * 4;
    float4 v = *(const float4*)(src + i);
    *(__half2*)(dst + i)     = __floats2half2_rn(fmaxf(v.x, 0.f), fmaxf(v.y, 0.f));
    *(__half2*)(dst + i + 2) = __floats2half2_rn(fmaxf(v.z, 0.f), fmaxf(v.w, 0.f));
}

// ---------------- h0 init (fp16 copy for GEMM A input) ----------------
__global__ void k_hinit(const float* __restrict__ src) {
    int i = (blockIdx.x * 256 + threadIdx.x) * 4;
    float4 v = *(const float4*)(src + i);
    *(__half2*)(g_h16a + i)     = __floats2half2_rn(v.x, v.y);
    *(__half2*)(g_h16a + i + 2) = __floats2half2_rn(v.z, v.w);
}

// ---------------- fp16 MMA GEMM: C[M,N] = A[M,K] @ B[N,K]^T + bias ----------------
// BM=128, BN=128, BK=32, 4-stage cp.async pipeline, 256 threads (8 warps, warp tile 64x32)
#define G2_STG   (128 * 40)            // halves per tile per stage
#define G2_SMEM  (4 * 2 * G2_STG * 2)  // bytes: 4 stages x (A+B) x 2B
__global__ __launch_bounds__(256, 2) void k_gemm2(int aSel, int bSel,
                                                  const float* __restrict__ bias,
                                                  int cSel, float* __restrict__ Cext, int ldc) {
    extern __shared__ __align__(16) char g2_raw[];
    __half* smA = (__half*)g2_raw;               // [4][128*40]
    __half* smB = smA + 4 * G2_STG;              // [4][128*40]

    const __half* A  = (aSel == 0) ? g_x16a : g_x16b;
    const __half* Bw = (bSel < 3) ? (g_Wih16 + (size_t)bSel * K3H * HID) : g_Wout16;
    float* C = (cSel == 0) ? g_xp : Cext;

    const int tid = threadIdx.x;
    const int bn = blockIdx.x, bm = blockIdx.y;
    const int lane = tid & 31, warp = tid >> 5;
    const int g = lane >> 2, tg = lane & 3;
    const int wy = warp >> 2, wx = warp & 3;   // wy 0..1 (64 rows), wx 0..3 (32 cols)

    const int ldr = tid >> 2;          // 0..63
    const int seg = (tid & 3) * 8;     // half offset within 32-half chunk
    const __half* gA0 = A  + (size_t)(bm * 128 + ldr) * HID + seg;
    const __half* gA1 = A  + (size_t)(bm * 128 + 64 + ldr) * HID + seg;
    const __half* gB0 = Bw + (size_t)(bn * 128 + ldr) * HID + seg;
    const __half* gB1 = Bw + (size_t)(bn * 128 + 64 + ldr) * HID + seg;
    const uint32_t dA0 = smem_u32(&smA[ldr * 40 + seg]);
    const uint32_t dA1 = smem_u32(&smA[(64 + ldr) * 40 + seg]);
    const uint32_t dB0 = smem_u32(&smB[ldr * 40 + seg]);
    const uint32_t dB1 = smem_u32(&smB[(64 + ldr) * 40 + seg]);
    const int stgB = G2_STG * 2;       // stage stride in bytes

    const int NK = HID / 32;           // 32

    // prologue: stages 0..2
#pragma unroll
    for (int s = 0; s < 3; ++s) {
        cp16(dA0 + s * stgB, gA0 + s * 32);
        cp16(dA1 + s * stgB, gA1 + s * 32);
        cp16(dB0 + s * stgB, gB0 + s * 32);
        cp16(dB1 + s * stgB, gB1 + s * 32);
        cp_commit();
    }

    float acc[4][4][4] = {};
    for (int kc = 0; kc < NK; ++kc) {
        asm volatile("cp.async.wait_group 2;\n" ::: "memory");
        __syncthreads();
        if (kc + 3 < NK) {
            int s = (kc + 3) & 3;
            cp16(dA0 + s * stgB, gA0 + (kc + 3) * 32);
            cp16(dA1 + s * stgB, gA1 + (kc + 3) * 32);
            cp16(dB0 + s * stgB, gB0 + (kc + 3) * 32);
            cp16(dB1 + s * stgB, gB1 + (kc + 3) * 32);
        }
        cp_commit();   // constant one group per iteration (possibly empty)

        const __half* As = smA + (kc & 3) * G2_STG;
        const __half* Bs = smB + (kc & 3) * G2_STG;
#pragma unroll
        for (int kk = 0; kk < 32; kk += 16) {
            uint32_t a[4][4], bb[4][2];
#pragma unroll
            for (int mt = 0; mt < 4; ++mt) {
                int r0 = wy * 64 + mt * 16 + g;
                a[mt][0] = *(const uint32_t*)&As[r0 * 40 + kk + tg * 2];
                a[mt][1] = *(const uint32_t*)&As[(r0 + 8) * 40 + kk + tg * 2];
                a[mt][2] = *(const uint32_t*)&As[r0 * 40 + kk + tg * 2 + 8];
                a[mt][3] = *(const uint32_t*)&As[(r0 + 8) * 40 + kk + tg * 2 + 8];
            }
#pragma unroll
            for (int nt = 0; nt < 4; ++nt) {
                int c0 = wx * 32 + nt * 8 + g;
                bb[nt][0] = *(const uint32_t*)&Bs[c0 * 40 + kk + tg * 2];
                bb[nt][1] = *(const uint32_t*)&Bs[c0 * 40 + kk + tg * 2 + 8];
            }
#pragma unroll
            for (int mt = 0; mt < 4; ++mt)
#pragma unroll
                for (int nt = 0; nt < 4; ++nt)
                    mma16816(acc[mt][nt], a[mt], bb[nt]);
        }
    }

#pragma unroll
    for (int mt = 0; mt < 4; ++mt) {
#pragma unroll
        for (int nt = 0; nt < 4; ++nt) {
            int row = bm * 128 + wy * 64 + mt * 16 + g;
            int col = bn * 128 + wx * 32 + nt * 8 + tg * 2;
            float b0 = bias[col], b1 = bias[col + 1];
            *(float2*)&C[(size_t)row * ldc + col] =
                make_float2(acc[mt][nt][0] + b0, acc[mt][nt][1] + b1);
            *(float2*)&C[(size_t)(row + 8) * ldc + col] =
                make_float2(acc[mt][nt][2] + b0, acc[mt][nt][3] + b1);
        }
    }
}

// ---------------- persistent GRU scan: all 32 timesteps of one layer ----------------
// 128 blocks x 256 threads. Block = (bh, cblk): batch half bh (32 rows), hidden cols
// [cblk*16,+16) x gates r,z,n (48 B-rows). W_hh slice resident in smem. Per step:
// stream this half's h (32x1024) with an 8-chunk-deep pipeline; 8 warps = 2m x 2n x
// 2k-parity (partials merged in smem); fused gate epilogue; split-phase grid barrier
// (arrive -> prefetch next xp -> poll).
#define SC_CH    (32 * 40)                 // halves per chunk buffer
#define SC_BS    (48 * 1032)               // halves
#define SC_AS    (12 * SC_CH)              // 3 supers x 4 chunks
#define SCAN_SMEM (SC_BS*2 + SC_AS*2 + 32*50*4 + 32*48*4 + 32*16*4)
__global__ __launch_bounds__(256) void k_gru_scan(int l, const float* __restrict__ bhh,
                                                  const float* __restrict__ enc,
                                                  float* __restrict__ finals) {
    extern __shared__ __align__(16) char smem_raw[];
    __half* Bs   = (__half*)smem_raw;            // 48 x 1032
    __half* As   = Bs + SC_BS;                   // 12 chunk bufs of 32 x 40
    float*  hp_s = (float*)(As + SC_AS);         // 32 x 50
    float*  xp_s = hp_s + 32 * 50;               // 32 x 48
    float*  h_own = xp_s + 32 * 48;              // 32 x 16

    const __half* Whh = g_Whh16 + (size_t)l * K3H * HID;
    __half* y16 = (l == 1) ? g_x16a : g_x16b;

    const int tid = threadIdx.x;
    const int cblk = blockIdx.x & 63;
    const int bh   = blockIdx.x >> 6;   // 0..1 batch half
    const int lane = tid & 31, warp = tid >> 5;
    const int g = lane >> 2, tg = lane & 3;
    const int wm = (warp >> 1) & 1, wn = warp & 1, ks = warp >> 2;

    unsigned bar_t = *(volatile unsigned*)&g_bar_gen;

    // load W_hh slice once: 48 rows x 1024 halves
    for (int i = tid; i < 48 * 128; i += 256) {
        int row = i >> 7;
        int c16 = (i & 127) << 3;
        int gate = row >> 4;
        size_t grow = (size_t)(gate * HID + cblk * 16 + (row & 15));
        cp16(smem_u32(&Bs[row * 1032 + c16]), Whh + grow * HID + c16);
    }
    cp_commit();

    // init block-private fp32 h columns
    for (int i = tid; i < 32 * 16; i += 256) {
        int b = i >> 4, jl = i & 15;
        h_own[i] = enc[(size_t)(bh * 32 + b) * HID + cblk * 16 + jl];
    }

    // per-thread A-load mapping: thread loads chunks {c2, c2+2} of each super
    const int c2  = tid >> 7;          // 0..1
    const int tt  = tid & 127;
    const int arow = tt >> 2;          // 0..31
    const int aseg = (tt & 3) * 8;
    const uint32_t dA_base = smem_u32(&As[arow * 40 + aseg]);

    // xp prefetch for step 0
    for (int e = tid; e < 384; e += 256) {
        int b = e / 12, rem = e % 12;
        int gate = rem >> 2, sg4 = (rem & 3) * 4;
        cp16(smem_u32(&xp_s[b * 48 + gate * 16 + sg4]),
             g_xp + ((size_t)((bh * 32 + b) * NT + 0)) * K3H + gate * HID + cblk * 16 + sg4);
    }
    cp_commit();

    for (int t = 0; t < NT; ++t) {
        const __half* h16in = (t & 1) ? g_h16b : g_h16a;
        __half* h16out      = (t & 1) ? g_h16a : g_h16b;
        const __half* gA = h16in + (size_t)(bh * 32 + arow) * HID + aseg;

        // prologue: supers 0,1
#pragma unroll
        for (int s = 0; s < 2; ++s) {
#pragma unroll
            for (int p = 0; p < 2; ++p) {
                int c = c2 + p * 2;
                cp16(dA_base + (s * 4 + c) * (SC_CH * 2), gA + (s * 4 + c) * 32);
            }
            cp_commit();
        }

        float acc[3][4] = {};
        for (int sb = 0; sb < 8; ++sb) {
            asm volatile("cp.async.wait_group 1;\n" ::: "memory");
            __syncthreads();
            if (sb + 2 < 8) {
                int sbuf = (sb + 2) % 3;
#pragma unroll
                for (int p = 0; p < 2; ++p) {
                    int c = c2 + p * 2;
                    cp16(dA_base + (sbuf * 4 + c) * (SC_CH * 2), gA + ((sb + 2) * 4 + c) * 32);
                }
            }
            cp_commit();
            const int sbase = (sb % 3) * 4;
#pragma unroll
            for (int p = 0; p < 2; ++p) {
                const int cc = ks + p * 2;   // k-parity split across warps
                const __half* Ac = As + (sbase + cc) * SC_CH;
                const __half* Bc = Bs + (sb * 4 + cc) * 32;
#pragma unroll
                for (int kk = 0; kk < 32; kk += 16) {
                    uint32_t a[4], bb[3][2];
                    int r0 = wm * 16 + g;
                    a[0] = *(const uint32_t*)&Ac[r0 * 40 + kk + tg * 2];
                    a[1] = *(const uint32_t*)&Ac[(r0 + 8) * 40 + kk + tg * 2];
                    a[2] = *(const uint32_t*)&Ac[r0 * 40 + kk + tg * 2 + 8];
                    a[3] = *(const uint32_t*)&Ac[(r0 + 8) * 40 + kk + tg * 2 + 8];
#pragma unroll
                    for (int nt = 0; nt < 3; ++nt) {
                        int c0 = wn * 24 + nt * 8 + g;
                        bb[nt][0] = *(const uint32_t*)&Bc[c0 * 1032 + kk + tg * 2];
                        bb[nt][1] = *(const uint32_t*)&Bc[c0 * 1032 + kk + tg * 2 + 8];
                    }
#pragma unroll
                    for (int nt = 0; nt < 3; ++nt) mma16816(acc[nt], a, bb[nt]);
                }
            }
        }

        // merge k-parity partials in smem: ks=0 writes, ks=1 adds
        if (ks == 0) {
#pragma unroll
            for (int nt = 0; nt < 3; ++nt) {
                int row = wm * 16 + g, col = wn * 24 + nt * 8 + tg * 2;
                *(float2*)&hp_s[row * 50 + col]       = make_float2(acc[nt][0], acc[nt][1]);
                *(float2*)&hp_s[(row + 8) * 50 + col] = make_float2(acc[nt][2], acc[nt][3]);
            }
        }
        __syncthreads();
        if (ks == 1) {
#pragma unroll
            for (int nt = 0; nt < 3; ++nt) {
                int row = wm * 16 + g, col = wn * 24 + nt * 8 + tg * 2;
                float2 v0 = *(float2*)&hp_s[row * 50 + col];
                float2 v1 = *(float2*)&hp_s[(row + 8) * 50 + col];
                v0.x += acc[nt][0]; v0.y += acc[nt][1];
                v1.x += acc[nt][2]; v1.y += acc[nt][3];
                *(float2*)&hp_s[row * 50 + col]       = v0;
                *(float2*)&hp_s[(row + 8) * 50 + col] = v1;
            }
        }
        __syncthreads();

#pragma unroll
        for (int i = 0; i < 2; ++i) {
            int idx = tid + i * 256;        // 0..511
            int b = idx >> 4, jl = idx & 15;
            int gb = bh * 32 + b;
            int j = cblk * 16 + jl;
            float hr = hp_s[b * 50 + jl]      + bhh[j];
            float hz = hp_s[b * 50 + 16 + jl] + bhh[HID + j];
            float hn = hp_s[b * 50 + 32 + jl] + bhh[2 * HID + j];
            float r = 1.f / (1.f + __expf(-(xp_s[b * 48 + jl] + hr)));
            float z = 1.f / (1.f + __expf(-(xp_s[b * 48 + 16 + jl] + hz)));
            float nn = tanhf(xp_s[b * 48 + 32 + jl] + r * hn);
            float ho = h_own[idx];
            float hnew = (1.f - z) * nn + z * ho;
            h_own[idx] = hnew;
            h16out[(size_t)gb * HID + j] = __float2half(hnew);
            y16[((size_t)(gb * NT + t)) * HID + j] = __float2half(hnew);
            if (t == NT - 1) finals[(size_t)gb * HID + j] = hnew;
        }

        // split-phase grid barrier: arrive, prefetch next xp, poll
        bar_t++;
        __syncthreads();
        if (tid == 0) {
            __threadfence();
            unsigned a = atomicAdd(&g_bar_cnt, 1);
            if (a == gridDim.x - 1) {
                g_bar_cnt = 0;
                __threadfence();
                atomicExch(&g_bar_gen, bar_t);
            }
        }
        if (t + 1 < NT) {
            for (int e = tid; e < 384; e += 256) {
                int b = e / 12, rem = e % 12;
                int gate = rem >> 2, sg4 = (rem & 3) * 4;
                cp16(smem_u32(&xp_s[b * 48 + gate * 16 + sg4]),
                     g_xp + ((size_t)((bh * 32 + b) * NT + t + 1)) * K3H + gate * HID + cblk * 16 + sg4);
            }
            cp_commit();
        }
        if (tid == 0) {
            while (*(volatile unsigned*)&g_bar_gen < bar_t) { }
            __threadfence();
        }
        __syncthreads();
    }
}

// ---------------- in-place log_softmax over V per row ----------------
__global__ __launch_bounds__(1024) void k_logsoftmax(float* __restrict__ p) {
    float* base = p + (size_t)blockIdx.x * VOC;
    const int tid = threadIdx.x;
    const int warp = tid >> 5, lane = tid & 31;
    __shared__ float red[32];

    float v[32];
    float m = -1e30f;
#pragma unroll
    for (int i = 0; i < 32; ++i) {
        int idx = tid + i * 1024;
        v[i] = (idx < VOC) ? base[idx] : -1e30f;
        m = fmaxf(m, v[i]);
    }
#pragma unroll
    for (int off = 16; off; off >>= 1) m = fmaxf(m, __shfl_xor_sync(0xffffffffu, m, off));
    if (lane == 0) red[warp] = m;
    __syncthreads();
    if (warp == 0) {
        float x = red[lane];
#pragma unroll
        for (int off = 16; off; off >>= 1) x = fmaxf(x, __shfl_xor_sync(0xffffffffu, x, off));
        red[lane] = x;
    }
    __syncthreads();
    m = red[0];
    __syncthreads();

    float s = 0.f;
#pragma unroll
    for (int i = 0; i < 32; ++i) s += __expf(v[i] - m);
#pragma unroll
    for (int off = 16; off; off >>= 1) s += __shfl_xor_sync(0xffffffffu, s, off);
    if (lane == 0) red[warp] = s;
    __syncthreads();
    if (warp == 0) {
        float x = red[lane];
#pragma unroll
        for (int off = 16; off; off >>= 1) x += __shfl_xor_sync(0xffffffffu, x, off);
        red[lane] = x;
    }
    __syncthreads();
    s = red[0];

    float lse = m + logf(s);
#pragma unroll
    for (int i = 0; i < 32; ++i) {
        int idx = tid + i * 1024;
        if (idx < VOC) base[idx] = v[i] - lse;
    }
}

// ---------------- launch ----------------
extern "C" void kernel_launch(void* const* d_in, const int* in_sizes, int n_in,
                              void* d_out, int out_size) {
    const float* enc_hidden = (const float*)d_in[1];
    const int*   target     = (const int*)d_in[2];
    const float* emb        = (const float*)d_in[3];
    const float* W_ih       = (const float*)d_in[4];
    const float* W_hh       = (const float*)d_in[5];
    const float* b_ih       = (const float*)d_in[6];
    const float* b_hh       = (const float*)d_in[7];
    const float* W_out      = (const float*)d_in[8];
    const float* b_out      = (const float*)d_in[9];
    float* out = (float*)d_out;

    cudaFuncSetAttribute(k_gru_scan, cudaFuncAttributeMaxDynamicSharedMemorySize, SCAN_SMEM);
    cudaFuncSetAttribute(k_gemm2, cudaFuncAttributeMaxDynamicSharedMemorySize, G2_SMEM);

    // 1) convert weights to fp16
    {
        int n1 = NL * K3H * HID;
        k_cvt<<<(n1 / 4 + 255) / 256, 256>>>(W_ih, 0, n1);
        k_cvt<<<(n1 / 4 + 255) / 256, 256>>>(W_hh, 1, n1);
        int n2 = VOC * HID;
        k_cvt<<<(n2 / 4 + 255) / 256, 256>>>(W_out, 2, n2);
    }

    // 2) embedding + relu
    k_embed<<<NB * NT, 256>>>(emb, target);

    // 3) layers: xp GEMM + persistent fused scan
    for (int l = 0; l < NL; ++l) {
        const float* enc_l = enc_hidden + (size_t)l * NB * HID;
        k_hinit<<<(NB * HID / 4) / 256, 256>>>(enc_l);
        int aSel = (l == 1) ? 1 : 0;
        k_gemm2<<<dim3(K3H / 128, (NB * NT) / 128), 256, G2_SMEM>>>(
            aSel, l, b_ih + (size_t)l * K3H, 0, nullptr, K3H);
        float* finals = out + (size_t)NB * NT * VOC + (size_t)l * NB * HID;
        k_gru_scan<<<128, 256, SCAN_SMEM>>>(l, b_hh + (size_t)l * K3H, enc_l, finals);
    }

    // 4) output GEMM (logits into d_out) + log_softmax in place
    k_gemm2<<<dim3(VOC / 128, (NB * NT) / 128), 256, G2_SMEM>>>(1, 3, b_out, 1, out, VOC);
    k_logsoftmax<<<NB * NT, 1024>>>(out);
}

// round 6
// speedup vs baseline: 1.3989x; 1.3989x over previous
#include <cuda_runtime.h>
#include <cuda_fp16.h>
#include <cstdint>

#define HID 1024
#define VOC 32000
#define NL  3
#define NB  64
#define NT  32
#define K3H (3*HID)

// ---------------- device scratch (static, allocation-free) ----------------
__device__ __align__(16) __half g_Wih16[NL * K3H * HID];
__device__ __align__(16) __half g_Whh16[NL * K3H * HID];
__device__ __align__(16) __half g_Wout16[VOC * HID];
__device__ __align__(16) __half g_x16a[NB * NT * HID];
__device__ __align__(16) __half g_x16b[NB * NT * HID];
__device__ __align__(16) float  g_xp[NB * NT * K3H];
__device__ __align__(16) __half g_h16a[NB * HID];
__device__ __align__(16) __half g_h16b[NB * HID];

// grid barrier state (generation-based; never needs host reset)
__device__ unsigned g_bar_cnt = 0;
__device__ unsigned g_bar_gen = 0;

// ---------------- helpers ----------------
__device__ __forceinline__ uint32_t smem_u32(const void* p) {
    return (uint32_t)__cvta_generic_to_shared(p);
}
__device__ __forceinline__ void cp16(uint32_t d, const void* s) {
    asm volatile("cp.async.cg.shared.global [%0], [%1], 16;\n" :: "r"(d), "l"(s));
}
__device__ __forceinline__ void cp_commit() {
    asm volatile("cp.async.commit_group;\n" ::: "memory");
}
__device__ __forceinline__ void mma16816(float* c, const uint32_t* a, const uint32_t* b) {
    asm volatile(
        "mma.sync.aligned.m16n8k16.row.col.f32.f16.f16.f32 "
        "{%0,%1,%2,%3},{%4,%5,%6,%7},{%8,%9},{%0,%1,%2,%3};\n"
        : "+f"(c[0]), "+f"(c[1]), "+f"(c[2]), "+f"(c[3])
        : "r"(a[0]), "r"(a[1]), "r"(a[2]), "r"(a[3]), "r"(b[0]), "r"(b[1]));
}
__device__ __forceinline__ void ldsm4(uint32_t& r0, uint32_t& r1, uint32_t& r2, uint32_t& r3,
                                      uint32_t a) {
    asm volatile("ldmatrix.sync.aligned.m8n8.x4.shared.b16 {%0,%1,%2,%3},[%4];\n"
                 : "=r"(r0), "=r"(r1), "=r"(r2), "=r"(r3) : "r"(a));
}
__device__ __forceinline__ void ldsm2(uint32_t& r0, uint32_t& r1, uint32_t a) {
    asm volatile("ldmatrix.sync.aligned.m8n8.x2.shared.b16 {%0,%1},[%2];\n"
                 : "=r"(r0), "=r"(r1) : "r"(a));
}

__device__ __forceinline__ void grid_sync(unsigned target) {
    __syncthreads();
    if (threadIdx.x == 0) {
        __threadfence();
        unsigned a = atomicAdd(&g_bar_cnt, 1);
        if (a == gridDim.x - 1) {
            g_bar_cnt = 0;
            __threadfence();
            atomicExch(&g_bar_gen, target);
        } else {
            while (*(volatile unsigned*)&g_bar_gen < target) { }
        }
        __threadfence();
    }
    __syncthreads();
}

// ---------------- f32 -> f16 weight convert ----------------
__global__ void k_cvt(const float* __restrict__ src, int dstSel, int n) {
    int i = (blockIdx.x * 256 + threadIdx.x) * 4;
    if (i >= n) return;
    __half* dst = (dstSel == 0) ? g_Wih16 : (dstSel == 1) ? g_Whh16 : g_Wout16;
    float4 v = *(const float4*)(src + i);
    *(__half2*)(dst + i)     = __floats2half2_rn(v.x, v.y);
    *(__half2*)(dst + i + 2) = __floats2half2_rn(v.z, v.w);
}

// ---------------- embedding + relu -> x16a ----------------
__global__ void k_embed(const float* __restrict__ emb, const int* __restrict__ target) {
    int row = blockIdx.x;           // 0..NB*NT-1
    int b = row >> 5, t = row & 31; // NT = 32
    int id = (t == 0) ? 0 : target[b * NT + t - 1];
    const float* src = emb + (size_t)id * HID;
    __half* dst = g_x16a + (size_t)row * HID;
    int i = threadIdx.x * 4;
    float4 v = *(const float4*)(src + i);
    *(__half2*)(dst + i)     = __floats2half2_rn(fmaxf(v.x, 0.f), fmaxf(v.y, 0.f));
    *(__half2*)(dst + i + 2) = __floats2half2_rn(fmaxf(v.z, 0.f), fmaxf(v.w, 0.f));
}

// ---------------- h0 init (fp16 copy for GEMM A input) ----------------
__global__ void k_hinit(const float* __restrict__ src) {
    int i = (blockIdx.x * 256 + threadIdx.x) * 4;
    float4 v = *(const float4*)(src + i);
    *(__half2*)(g_h16a + i)     = __floats2half2_rn(v.x, v.y);
    *(__half2*)(g_h16a + i + 2) = __floats2half2_rn(v.z, v.w);
}

// ---------------- fp16 MMA GEMM: C[M,N] = A[M,K] @ B[N,K]^T + bias ----------------
// BM=128, BN=128, BK=32, 4-stage cp.async pipeline, 256 threads (8 warps, warp tile 64x32)
// Fragment loads via ldmatrix (conflict-free with 40-half row stride).
#define G2_STG   (128 * 40)            // halves per tile per stage
#define G2_SMEM  (4 * 2 * G2_STG * 2)  // bytes: 4 stages x (A+B) x 2B
__global__ __launch_bounds__(256, 2) void k_gemm2(int aSel, int bSel,
                                                  const float* __restrict__ bias,
                                                  int cSel, float* __restrict__ Cext, int ldc) {
    extern __shared__ __align__(16) char g2_raw[];
    __half* smA = (__half*)g2_raw;               // [4][128*40]
    __half* smB = smA + 4 * G2_STG;              // [4][128*40]

    const __half* A  = (aSel == 0) ? g_x16a : g_x16b;
    const __half* Bw = (bSel < 3) ? (g_Wih16 + (size_t)bSel * K3H * HID) : g_Wout16;
    float* C = (cSel == 0) ? g_xp : Cext;

    const int tid = threadIdx.x;
    const int bn = blockIdx.x, bm = blockIdx.y;
    const int lane = tid & 31, warp = tid >> 5;
    const int g = lane >> 2, tg = lane & 3;
    const int wy = warp >> 2, wx = warp & 3;   // wy 0..1 (64 rows), wx 0..3 (32 cols)

    const int ldr = tid >> 2;          // 0..63
    const int seg = (tid & 3) * 8;     // half offset within 32-half chunk
    const __half* gA0 = A  + (size_t)(bm * 128 + ldr) * HID + seg;
    const __half* gA1 = A  + (size_t)(bm * 128 + 64 + ldr) * HID + seg;
    const __half* gB0 = Bw + (size_t)(bn * 128 + ldr) * HID + seg;
    const __half* gB1 = Bw + (size_t)(bn * 128 + 64 + ldr) * HID + seg;
    const uint32_t dA0 = smem_u32(&smA[ldr * 40 + seg]);
    const uint32_t dA1 = smem_u32(&smA[(64 + ldr) * 40 + seg]);
    const uint32_t dB0 = smem_u32(&smB[ldr * 40 + seg]);
    const uint32_t dB1 = smem_u32(&smB[(64 + ldr) * 40 + seg]);
    const int stgB = G2_STG * 2;       // stage stride in bytes

    // ldmatrix per-lane byte offsets (within a stage)
    uint32_t aoff[4], boff[2];
#pragma unroll
    for (int mt = 0; mt < 4; ++mt)
        aoff[mt] = ((wy * 64 + mt * 16 + (lane & 15)) * 40 + (lane >> 4) * 8) * 2;
#pragma unroll
    for (int np = 0; np < 2; ++np)
        boff[np] = ((wx * 32 + np * 16 + (lane & 7) + ((lane & 16) >> 1)) * 40 +
                    ((lane >> 3) & 1) * 8) * 2;
    const uint32_t smA_u = smem_u32(smA);
    const uint32_t smB_u = smem_u32(smB);

    const int NK = HID / 32;           // 32

    // prologue: stages 0..2
#pragma unroll
    for (int s = 0; s < 3; ++s) {
        cp16(dA0 + s * stgB, gA0 + s * 32);
        cp16(dA1 + s * stgB, gA1 + s * 32);
        cp16(dB0 + s * stgB, gB0 + s * 32);
        cp16(dB1 + s * stgB, gB1 + s * 32);
        cp_commit();
    }

    float acc[4][4][4] = {};
    for (int kc = 0; kc < NK; ++kc) {
        asm volatile("cp.async.wait_group 2;\n" ::: "memory");
        __syncthreads();
        if (kc + 3 < NK) {
            int s = (kc + 3) & 3;
            cp16(dA0 + s * stgB, gA0 + (kc + 3) * 32);
            cp16(dA1 + s * stgB, gA1 + (kc + 3) * 32);
            cp16(dB0 + s * stgB, gB0 + (kc + 3) * 32);
            cp16(dB1 + s * stgB, gB1 + (kc + 3) * 32);
        }
        cp_commit();   // constant one group per iteration (possibly empty)

        const uint32_t Abase = smA_u + (kc & 3) * stgB;
        const uint32_t Bbase = smB_u + (kc & 3) * stgB;
#pragma unroll
        for (int kk = 0; kk < 32; kk += 16) {
            uint32_t a[4][4], bb[4][2];
#pragma unroll
            for (int mt = 0; mt < 4; ++mt)
                ldsm4(a[mt][0], a[mt][1], a[mt][2], a[mt][3], Abase + aoff[mt] + kk * 2);
#pragma unroll
            for (int np = 0; np < 2; ++np)
                ldsm4(bb[np * 2][0], bb[np * 2][1], bb[np * 2 + 1][0], bb[np * 2 + 1][1],
                      Bbase + boff[np] + kk * 2);
#pragma unroll
            for (int mt = 0; mt < 4; ++mt)
#pragma unroll
                for (int nt = 0; nt < 4; ++nt)
                    mma16816(acc[mt][nt], a[mt], bb[nt]);
        }
    }

#pragma unroll
    for (int mt = 0; mt < 4; ++mt) {
#pragma unroll
        for (int nt = 0; nt < 4; ++nt) {
            int row = bm * 128 + wy * 64 + mt * 16 + g;
            int col = bn * 128 + wx * 32 + nt * 8 + tg * 2;
            float b0 = bias[col], b1 = bias[col + 1];
            *(float2*)&C[(size_t)row * ldc + col] =
                make_float2(acc[mt][nt][0] + b0, acc[mt][nt][1] + b1);
            *(float2*)&C[(size_t)(row + 8) * ldc + col] =
                make_float2(acc[mt][nt][2] + b0, acc[mt][nt][3] + b1);
        }
    }
}

// ---------------- persistent GRU scan: all 32 timesteps of one layer ----------------
// 64 blocks x 256 threads (R4 design). Block cblk owns hidden cols [cblk*16,+16)
// for gates r,z,n. W_hh slice (48x1024) resident in smem. Per step: h streamed with
// 8-deep cp.async pipeline (3 super-buffers of 4 chunks), xp slice prefetched to
// smem, fp32 h kept in smem, fused gate epilogue + grid barrier. ldmatrix fragments.
#define SC_CH    2560                      // halves per 64x40 chunk
#define SC_BS    (48 * 1032)               // halves
#define SC_AS    (12 * SC_CH)              // halves (3 supers x 4 chunks)
#define SCAN_SMEM (SC_BS*2 + SC_AS*2 + 64*50*4 + 64*48*4 + 64*16*4)
__global__ __launch_bounds__(256) void k_gru_scan(int l, const float* __restrict__ bhh,
                                                  const float* __restrict__ enc,
                                                  float* __restrict__ finals) {
    extern __shared__ __align__(16) char smem_raw[];
    __half* Bs   = (__half*)smem_raw;            // 48 x 1032
    __half* As   = Bs + SC_BS;                   // 12 chunk bufs of 64 x 40
    float*  hp_s = (float*)(As + SC_AS);         // 64 x 50
    float*  xp_s = hp_s + 64 * 50;               // 64 x 48
    float*  h_own = xp_s + 64 * 48;              // 64 x 16 (block's fp32 h cols)

    const __half* Whh = g_Whh16 + (size_t)l * K3H * HID;
    __half* y16 = (l == 1) ? g_x16a : g_x16b;

    const int tid = threadIdx.x;
    const int cblk = blockIdx.x; // 0..63
    const int lane = tid & 31, warp = tid >> 5;
    const int g = lane >> 2, tg = lane & 3;
    const int wm = warp >> 1, wn = warp & 1;   // wm 0..3 (64 rows), wn 0..1 (48 cols)

    unsigned bar_t = *(volatile unsigned*)&g_bar_gen;

    // load W_hh slice once: 48 rows x 1024 halves
    for (int i = tid; i < 48 * 128; i += 256) {
        int row = i >> 7;             // 0..47
        int c16 = (i & 127) << 3;     // half offset, step 8
        int gate = row >> 4;
        size_t grow = (size_t)(gate * HID + cblk * 16 + (row & 15));
        cp16(smem_u32(&Bs[row * 1032 + c16]), Whh + grow * HID + c16);
    }
    cp_commit();

    // init block-private fp32 h columns from encoder_hidden
    for (int i = tid; i < 64 * 16; i += 256) {
        int b = i >> 4, jl = i & 15;
        h_own[i] = enc[(size_t)b * HID + cblk * 16 + jl];
    }

    const int ldr = tid >> 2;         // 0..63 (batch row)
    const int seg = (tid & 3) * 8;
    const uint32_t dA_base = smem_u32(&As[ldr * 40 + seg]);

    // ldmatrix per-lane byte offsets
    const uint32_t aoff  = ((wm * 16 + (lane & 15)) * 40 + (lane >> 4) * 8) * 2;
    const uint32_t boff4 = ((wn * 24 + (lane & 7) + ((lane & 16) >> 1)) * 1032 +
                            ((lane >> 3) & 1) * 8) * 2;
    const uint32_t boff2 = ((wn * 24 + 16 + (lane & 7)) * 1032 +
                            ((lane >> 3) & 1) * 8) * 2;
    const uint32_t As_u = smem_u32(As);
    const uint32_t Bs_u = smem_u32(Bs);

    for (int t = 0; t < NT; ++t) {
        const __half* h16in = (t & 1) ? g_h16b : g_h16a;
        __half* h16out      = (t & 1) ? g_h16a : g_h16b;
        const __half* gA = h16in + (size_t)ldr * HID + seg;

        // prefetch xp slice for this step: 64 b x 3 gates x 16 floats
        for (int e = tid; e < 768; e += 256) {
            int b = e / 12, rem = e % 12;
            int gate = rem >> 2, sg = rem & 3;
            cp16(smem_u32(&xp_s[b * 48 + gate * 16 + sg * 4]),
                 g_xp + ((size_t)(b * NT + t)) * K3H + gate * HID + cblk * 16 + sg * 4);
        }
        cp_commit();

        // prologue: supers 0,1 (4 chunks each)
#pragma unroll
        for (int s = 0; s < 2; ++s) {
#pragma unroll
            for (int c = 0; c < 4; ++c)
                cp16(dA_base + (s * 4 + c) * (SC_CH * 2), gA + (s * 4 + c) * 32);
            cp_commit();
        }

        float acc[3][4] = {};
        for (int sb = 0; sb < 8; ++sb) {
            asm volatile("cp.async.wait_group 1;\n" ::: "memory");  // super sb landed
            __syncthreads();                                        // done reading sb-1's buf
            if (sb + 2 < 8) {
                int sbuf = (sb + 2) % 3;
#pragma unroll
                for (int c = 0; c < 4; ++c)
                    cp16(dA_base + (sbuf * 4 + c) * (SC_CH * 2), gA + ((sb + 2) * 4 + c) * 32);
            }
            cp_commit();   // constant group count
            const int sbase = (sb % 3) * 4;
#pragma unroll
            for (int cc = 0; cc < 4; ++cc) {
                const uint32_t Ab = As_u + (sbase + cc) * (SC_CH * 2) + aoff;
                const uint32_t Bb = Bs_u + (sb * 4 + cc) * 64 + boff4;   // 32 halves = 64B
                const uint32_t Bb2 = Bs_u + (sb * 4 + cc) * 64 + boff2;
#pragma unroll
                for (int kk = 0; kk < 32; kk += 16) {
                    uint32_t a[4], bb[3][2];
                    ldsm4(a[0], a[1], a[2], a[3], Ab + kk * 2);
                    ldsm4(bb[0][0], bb[0][1], bb[1][0], bb[1][1], Bb + kk * 2);
                    ldsm2(bb[2][0], bb[2][1], Bb2 + kk * 2);
#pragma unroll
                    for (int nt = 0; nt < 3; ++nt) mma16816(acc[nt], a, bb[nt]);
                }
            }
        }

        // stage hp (64 x 48) so each thread sees its gate triple
#pragma unroll
        for (int nt = 0; nt < 3; ++nt) {
            int row = wm * 16 + g, col = wn * 24 + nt * 8 + tg * 2;
            *(float2*)&hp_s[row * 50 + col]       = make_float2(acc[nt][0], acc[nt][1]);
            *(float2*)&hp_s[(row + 8) * 50 + col] = make_float2(acc[nt][2], acc[nt][3]);
        }
        __syncthreads();

#pragma unroll
        for (int i = 0; i < 4; ++i) {
            int idx = tid + i * 256;        // 0..1023
            int b = idx >> 4, jl = idx & 15;
            int j = cblk * 16 + jl;
            float hr = hp_s[b * 50 + jl]      + bhh[j];
            float hz = hp_s[b * 50 + 16 + jl] + bhh[HID + j];
            float hn = hp_s[b * 50 + 32 + jl] + bhh[2 * HID + j];
            float r = 1.f / (1.f + __expf(-(xp_s[b * 48 + jl] + hr)));
            float z = 1.f / (1.f + __expf(-(xp_s[b * 48 + 16 + jl] + hz)));
            float nn = tanhf(xp_s[b * 48 + 32 + jl] + r * hn);
            float ho = h_own[idx];
            float hnew = (1.f - z) * nn + z * ho;
            h_own[idx] = hnew;
            h16out[(size_t)b * HID + j] = __float2half(hnew);
            y16[((size_t)(b * NT + t)) * HID + j] = __float2half(hnew);
            if (t == NT - 1) finals[(size_t)b * HID + j] = hnew;
        }

        bar_t++;
        grid_sync(bar_t);   // h published to all blocks before next timestep
    }
}

// ---------------- in-place log_softmax over V per row ----------------
__global__ __launch_bounds__(1024) void k_logsoftmax(float* __restrict__ p) {
    float* base = p + (size_t)blockIdx.x * VOC;
    const int tid = threadIdx.x;
    const int warp = tid >> 5, lane = tid & 31;
    __shared__ float red[32];

    float v[32];
    float m = -1e30f;
#pragma unroll
    for (int i = 0; i < 32; ++i) {
        int idx = tid + i * 1024;
        v[i] = (idx < VOC) ? base[idx] : -1e30f;
        m = fmaxf(m, v[i]);
    }
#pragma unroll
    for (int off = 16; off; off >>= 1) m = fmaxf(m, __shfl_xor_sync(0xffffffffu, m, off));
    if (lane == 0) red[warp] = m;
    __syncthreads();
    if (warp == 0) {
        float x = red[lane];
#pragma unroll
        for (int off = 16; off; off >>= 1) x = fmaxf(x, __shfl_xor_sync(0xffffffffu, x, off));
        red[lane] = x;
    }
    __syncthreads();
    m = red[0];
    __syncthreads();

    float s = 0.f;
#pragma unroll
    for (int i = 0; i < 32; ++i) s += __expf(v[i] - m);
#pragma unroll
    for (int off = 16; off; off >>= 1) s += __shfl_xor_sync(0xffffffffu, s, off);
    if (lane == 0) red[warp] = s;
    __syncthreads();
    if (warp == 0) {
        float x = red[lane];
#pragma unroll
        for (int off = 16; off; off >>= 1) x += __shfl_xor_sync(0xffffffffu, x, off);
        red[lane] = x;
    }
    __syncthreads();
    s = red[0];

    float lse = m + logf(s);
#pragma unroll
    for (int i = 0; i < 32; ++i) {
        int idx = tid + i * 1024;
        if (idx < VOC) base[idx] = v[i] - lse;
    }
}

// ---------------- launch ----------------
extern "C" void kernel_launch(void* const* d_in, const int* in_sizes, int n_in,
                              void* d_out, int out_size) {
    const float* enc_hidden = (const float*)d_in[1];
    const int*   target     = (const int*)d_in[2];
    const float* emb        = (const float*)d_in[3];
    const float* W_ih       = (const float*)d_in[4];
    const float* W_hh       = (const float*)d_in[5];
    const float* b_ih       = (const float*)d_in[6];
    const float* b_hh       = (const float*)d_in[7];
    const float* W_out      = (const float*)d_in[8];
    const float* b_out      = (const float*)d_in[9];
    float* out = (float*)d_out;

    cudaFuncSetAttribute(k_gru_scan, cudaFuncAttributeMaxDynamicSharedMemorySize, SCAN_SMEM);
    cudaFuncSetAttribute(k_gemm2, cudaFuncAttributeMaxDynamicSharedMemorySize, G2_SMEM);

    // 1) convert weights to fp16
    {
        int n1 = NL * K3H * HID;
        k_cvt<<<(n1 / 4 + 255) / 256, 256>>>(W_ih, 0, n1);
        k_cvt<<<(n1 / 4 + 255) / 256, 256>>>(W_hh, 1, n1);
        int n2 = VOC * HID;
        k_cvt<<<(n2 / 4 + 255) / 256, 256>>>(W_out, 2, n2);
    }

    // 2) embedding + relu
    k_embed<<<NB * NT, 256>>>(emb, target);

    // 3) layers: xp GEMM + persistent fused scan
    for (int l = 0; l < NL; ++l) {
        const float* enc_l = enc_hidden + (size_t)l * NB * HID;
        k_hinit<<<(NB * HID / 4) / 256, 256>>>(enc_l);
        int aSel = (l == 1) ? 1 : 0;
        k_gemm2<<<dim3(K3H / 128, (NB * NT) / 128), 256, G2_SMEM>>>(
            aSel, l, b_ih + (size_t)l * K3H, 0, nullptr, K3H);
        float* finals = out + (size_t)NB * NT * VOC + (size_t)l * NB * HID;
        k_gru_scan<<<64, 256, SCAN_SMEM>>>(l, b_hh + (size_t)l * K3H, enc_l, finals);
    }

    // 4) output GEMM (logits into d_out) + log_softmax in place
    k_gemm2<<<dim3(VOC / 128, (NB * NT) / 128), 256, G2_SMEM>>>(1, 3, b_out, 1, out, VOC);
    k_logsoftmax<<<NB * NT, 1024>>>(out);
}